// round 1
// baseline (speedup 1.0000x reference)
#include <cuda_runtime.h>
#include <math.h>

// Problem constants
#define BATCH 4
#define CIN   2048
#define NPIX  2304      // 48*48
#define DHID  256

// GEMM tiling
#define BM 128
#define BN 128
#define BK 16
#define TM 8
#define TN 8
// threads per block = (BM/TM)*(BN/TN) = 256

// -------------------- scratch (static device globals, no allocs) -----------
__device__ float g_QL[(size_t)BATCH * NPIX * DHID];  // proj(left, wq)
__device__ float g_KR[(size_t)BATCH * NPIX * DHID];  // proj(right, wr)
__device__ float g_QR[(size_t)BATCH * NPIX * DHID];  // proj(right, wq)
__device__ float g_KL[(size_t)BATCH * NPIX * DHID];  // proj(left, wr)
__device__ float g_S [(size_t)BATCH * NPIX * NPIX];  // scores / attn (reused)

// ----------------------------------------------------------------------------
// C[m,n] = sum_k A[m,k] * B[n,k]  (+ bias[n])
// B is always row-major [N,K] (k contiguous).
// A layout:
//   A_KM = false : A row-major [M,K] (k contiguous), lda = row stride
//   A_KM = true  : A is [K,M] (m contiguous), lda = stride between k rows
// All of M, N divisible by 128; K divisible by 16. No bounds checks.
// ----------------------------------------------------------------------------
template <bool A_KM>
__global__ __launch_bounds__(256)
void sgemm_nt(const float* __restrict__ A, const float* __restrict__ B,
              float* __restrict__ C, const float* __restrict__ bias,
              int M, int N, int K, int lda, int ldb, int ldc,
              long long strideA, long long strideB, long long strideC)
{
    __shared__ float As[BK][BM + 4];
    __shared__ float Bs[BK][BN + 4];

    const int b = blockIdx.z;
    A += (long long)b * strideA;
    B += (long long)b * strideB;
    C += (long long)b * strideC;

    const int n0 = blockIdx.x * BN;
    const int m0 = blockIdx.y * BM;
    const int tid = threadIdx.x;
    const int tx = tid % (BN / TN);   // 0..15
    const int ty = tid / (BN / TN);   // 0..15

    float acc[TM][TN];
#pragma unroll
    for (int i = 0; i < TM; ++i)
#pragma unroll
        for (int j = 0; j < TN; ++j) acc[i][j] = 0.f;

    for (int k0 = 0; k0 < K; k0 += BK) {
        // ---- load A tile ----
        if (A_KM) {
            // A[k, m], m contiguous: 16 k-rows x 32 float4 = 512 float4
#pragma unroll
            for (int r = 0; r < 2; ++r) {
                int idx = tid + r * 256;
                int k  = idx >> 5;       // /32
                int m4 = idx & 31;
                const float4 v = *reinterpret_cast<const float4*>(
                    &A[(long long)(k0 + k) * lda + m0 + m4 * 4]);
                *reinterpret_cast<float4*>(&As[k][m4 * 4]) = v;
            }
        } else {
            // A[m, k], k contiguous: 128 m-rows x 4 float4 = 512 float4
#pragma unroll
            for (int r = 0; r < 2; ++r) {
                int idx = tid + r * 256;
                int row = idx >> 2;
                int c4  = idx & 3;
                const float4 v = *reinterpret_cast<const float4*>(
                    &A[(long long)(m0 + row) * lda + k0 + c4 * 4]);
                As[c4 * 4 + 0][row] = v.x;
                As[c4 * 4 + 1][row] = v.y;
                As[c4 * 4 + 2][row] = v.z;
                As[c4 * 4 + 3][row] = v.w;
            }
        }
        // ---- load B tile (row-major [N,K], k contiguous) ----
#pragma unroll
        for (int r = 0; r < 2; ++r) {
            int idx = tid + r * 256;
            int row = idx >> 2;
            int c4  = idx & 3;
            const float4 v = *reinterpret_cast<const float4*>(
                &B[(long long)(n0 + row) * ldb + k0 + c4 * 4]);
            Bs[c4 * 4 + 0][row] = v.x;
            Bs[c4 * 4 + 1][row] = v.y;
            Bs[c4 * 4 + 2][row] = v.z;
            Bs[c4 * 4 + 3][row] = v.w;
        }
        __syncthreads();

#pragma unroll
        for (int kk = 0; kk < BK; ++kk) {
            float a[TM], bb[TN];
#pragma unroll
            for (int i = 0; i < TM; ++i) a[i] = As[kk][ty * TM + i];
#pragma unroll
            for (int j = 0; j < TN; ++j) bb[j] = Bs[kk][tx * TN + j];
#pragma unroll
            for (int i = 0; i < TM; ++i)
#pragma unroll
                for (int j = 0; j < TN; ++j)
                    acc[i][j] = fmaf(a[i], bb[j], acc[i][j]);
        }
        __syncthreads();
    }

    // ---- epilogue (+bias), float4 stores ----
    float bv[TN];
#pragma unroll
    for (int j = 0; j < TN; ++j)
        bv[j] = (bias != nullptr) ? bias[n0 + tx * TN + j] : 0.f;

#pragma unroll
    for (int i = 0; i < TM; ++i) {
        const int m = m0 + ty * TM + i;
        float* crow = &C[(long long)m * ldc + n0 + tx * TN];
#pragma unroll
        for (int j4 = 0; j4 < TN; j4 += 4) {
            float4 v;
            v.x = acc[i][j4 + 0] + bv[j4 + 0];
            v.y = acc[i][j4 + 1] + bv[j4 + 1];
            v.z = acc[i][j4 + 2] + bv[j4 + 2];
            v.w = acc[i][j4 + 3] + bv[j4 + 3];
            *reinterpret_cast<float4*>(crow + j4) = v;
        }
    }
}

// ----------------------------------------------------------------------------
// In-place row softmax. One block (256 threads) per row of length NPIX=2304.
// ----------------------------------------------------------------------------
__global__ __launch_bounds__(256)
void softmax_rows(float* __restrict__ S)
{
    const int PER = NPIX / 256;  // 9
    float* p = S + (long long)blockIdx.x * NPIX;
    const int tid = threadIdx.x;

    float v[PER];
    float mx = -INFINITY;
#pragma unroll
    for (int i = 0; i < PER; ++i) {
        v[i] = p[tid + i * 256];
        mx = fmaxf(mx, v[i]);
    }

    __shared__ float red[8];
#pragma unroll
    for (int o = 16; o; o >>= 1) mx = fmaxf(mx, __shfl_xor_sync(0xffffffffu, mx, o));
    if ((tid & 31) == 0) red[tid >> 5] = mx;
    __syncthreads();
    mx = red[0];
#pragma unroll
    for (int i = 1; i < 8; ++i) mx = fmaxf(mx, red[i]);
    __syncthreads();

    float s = 0.f;
#pragma unroll
    for (int i = 0; i < PER; ++i) {
        v[i] = __expf(v[i] - mx);
        s += v[i];
    }
#pragma unroll
    for (int o = 16; o; o >>= 1) s += __shfl_xor_sync(0xffffffffu, s, o);
    if ((tid & 31) == 0) red[tid >> 5] = s;
    __syncthreads();
    s = red[0];
#pragma unroll
    for (int i = 1; i < 8; ++i) s += red[i];

    const float inv = 1.f / s;
#pragma unroll
    for (int i = 0; i < PER; ++i) p[tid + i * 256] = v[i] * inv;
}

// ----------------------------------------------------------------------------
// Copy raw features [B, CIN, NPIX] into out tensor [B, 2*CIN, NPIX] channels 0..CIN-1
// ----------------------------------------------------------------------------
__global__ __launch_bounds__(256)
void copy_features(const float* __restrict__ src, float* __restrict__ dst)
{
    const long long perBatch4 = (long long)CIN * NPIX / 4;   // float4 units
    const long long total4 = (long long)BATCH * perBatch4;
    long long idx = (long long)blockIdx.x * blockDim.x + threadIdx.x;
    if (idx >= total4) return;
    long long b = idx / perBatch4;
    long long r = idx % perBatch4;
    const float4* s4 = reinterpret_cast<const float4*>(src);
    float4* d4 = reinterpret_cast<float4*>(dst);
    d4[b * ((long long)2 * CIN * NPIX / 4) + r] = s4[idx];
}

// ----------------------------------------------------------------------------
extern "C" void kernel_launch(void* const* d_in, const int* in_sizes, int n_in,
                              void* d_out, int out_size)
{
    const float* left  = (const float*)d_in[0];
    const float* right = (const float*)d_in[1];
    const float* wq    = (const float*)d_in[2];
    const float* bq    = (const float*)d_in[3];
    const float* wr    = (const float*)d_in[4];
    const float* br    = (const float*)d_in[5];
    float* out = (float*)d_out;

    float *QL, *KR, *QR, *KL, *S;
    cudaGetSymbolAddress((void**)&QL, g_QL);
    cudaGetSymbolAddress((void**)&KR, g_KR);
    cudaGetSymbolAddress((void**)&QR, g_QR);
    cudaGetSymbolAddress((void**)&KL, g_KL);
    cudaGetSymbolAddress((void**)&S,  g_S);

    const long long featStride = (long long)CIN * NPIX;     // per-batch feature stride
    const long long qkStride   = (long long)NPIX * DHID;
    const long long sStride    = (long long)NPIX * NPIX;
    const long long outStride  = (long long)2 * CIN * NPIX; // per-batch out stride
    const long long outHalf    = (long long)CIN * NPIX;     // offset of weighted half
    float* outL = out;
    float* outR = out + (long long)BATCH * outStride;

    // ---- 1. projections: Q[b,n,d] = sum_c X[b,c,n] * W[d,c] + bias[d] ----
    // A = features in [K=C, M=NPIX] layout (m contiguous) -> A_KM=true, lda=NPIX
    // B = W [D, C] (k contiguous), ldb=C; C = Q [NPIX, D], ldc=D
    {
        dim3 grid(DHID / BN, NPIX / BM, BATCH);  // 2 x 18 x 4
        sgemm_nt<true><<<grid, 256>>>(left,  wq, QL, bq, NPIX, DHID, CIN,
                                      NPIX, CIN, DHID, featStride, 0, qkStride);
        sgemm_nt<true><<<grid, 256>>>(right, wr, KR, br, NPIX, DHID, CIN,
                                      NPIX, CIN, DHID, featStride, 0, qkStride);
        sgemm_nt<true><<<grid, 256>>>(right, wq, QR, bq, NPIX, DHID, CIN,
                                      NPIX, CIN, DHID, featStride, 0, qkStride);
        sgemm_nt<true><<<grid, 256>>>(left,  wr, KL, br, NPIX, DHID, CIN,
                                      NPIX, CIN, DHID, featStride, 0, qkStride);
    }

    dim3 scoreGrid(NPIX / BN, NPIX / BM, BATCH);  // 18 x 18 x 4
    dim3 outGrid(NPIX / BN, CIN / BM, BATCH);     // 18 x 16 x 4
    const int copyBlocks = (int)(((long long)BATCH * CIN * NPIX / 4 + 255) / 256);

    // ---- direction 1: attend left over right ----
    // scores S[n,m] = sum_d QL[n,d] * KR[m,d]
    sgemm_nt<false><<<scoreGrid, 256>>>(QL, KR, S, nullptr, NPIX, NPIX, DHID,
                                        DHID, DHID, NPIX, qkStride, qkStride, sStride);
    softmax_rows<<<BATCH * NPIX, 256>>>(S);
    // out[c,n] = sum_m V[c,m] * attn[n,m]; V = right features
    sgemm_nt<false><<<outGrid, 256>>>(right, S, outL + outHalf, nullptr, CIN, NPIX, NPIX,
                                      NPIX, NPIX, NPIX, featStride, sStride, outStride);

    // ---- direction 2: attend right over left (reuses S; stream-ordered) ----
    sgemm_nt<false><<<scoreGrid, 256>>>(QR, KL, S, nullptr, NPIX, NPIX, DHID,
                                        DHID, DHID, NPIX, qkStride, qkStride, sStride);
    softmax_rows<<<BATCH * NPIX, 256>>>(S);
    sgemm_nt<false><<<outGrid, 256>>>(left, S, outR + outHalf, nullptr, CIN, NPIX, NPIX,
                                      NPIX, NPIX, NPIX, featStride, sStride, outStride);

    // ---- raw feature passthrough into channel block [0, CIN) ----
    copy_features<<<copyBlocks, 256>>>(left,  outL);
    copy_features<<<copyBlocks, 256>>>(right, outR);
}

// round 3
// speedup vs baseline: 2.3102x; 2.3102x over previous
#include <cuda_runtime.h>
#include <cuda_bf16.h>
#include <math.h>
#include <stdint.h>

typedef unsigned short u16;
typedef unsigned int   u32;
typedef unsigned long long u64;

#define BATCH 4
#define CIN   2048
#define NPIX  2304
#define DHID  256

// ---------------- scratch (static device globals; no allocations) ----------
__device__ u16 g_fLhi[(size_t)BATCH*CIN*NPIX];   // left features bf16 hi, [B][C][N]
__device__ u16 g_fLlo[(size_t)BATCH*CIN*NPIX];
__device__ u16 g_fRhi[(size_t)BATCH*CIN*NPIX];
__device__ u16 g_fRlo[(size_t)BATCH*CIN*NPIX];
__device__ u16 g_fTLhi[(size_t)BATCH*NPIX*CIN];  // transposed [B][N][C]
__device__ u16 g_fTLlo[(size_t)BATCH*NPIX*CIN];
__device__ u16 g_fTRhi[(size_t)BATCH*NPIX*CIN];
__device__ u16 g_fTRlo[(size_t)BATCH*NPIX*CIN];
__device__ u16 g_wqhi[(size_t)DHID*CIN];
__device__ u16 g_wqlo[(size_t)DHID*CIN];
__device__ u16 g_wrhi[(size_t)DHID*CIN];
__device__ u16 g_wrlo[(size_t)DHID*CIN];
__device__ u16 g_QLhi[(size_t)BATCH*NPIX*DHID];
__device__ u16 g_QLlo[(size_t)BATCH*NPIX*DHID];
__device__ u16 g_KRhi[(size_t)BATCH*NPIX*DHID];
__device__ u16 g_KRlo[(size_t)BATCH*NPIX*DHID];
__device__ u16 g_QRhi[(size_t)BATCH*NPIX*DHID];
__device__ u16 g_QRlo[(size_t)BATCH*NPIX*DHID];
__device__ u16 g_KLhi[(size_t)BATCH*NPIX*DHID];
__device__ u16 g_KLlo[(size_t)BATCH*NPIX*DHID];
__device__ float g_S[(size_t)BATCH*NPIX*NPIX];   // fp32 scores
__device__ u16 g_Ahi[(size_t)BATCH*NPIX*NPIX];   // attn bf16 hi
__device__ u16 g_Alo[(size_t)BATCH*NPIX*NPIX];

// ---------------- helpers ----------------------------------------------------
__device__ __forceinline__ u32 smem_u32(const void* p) {
    u32 a;
    asm("{ .reg .u64 t; cvta.to.shared.u64 t, %1; cvt.u32.u64 %0, t; }" : "=r"(a) : "l"(p));
    return a;
}
__device__ __forceinline__ void cp16(u32 dst, const void* src) {
    asm volatile("cp.async.cg.shared.global [%0], [%1], 16;" :: "r"(dst), "l"(src));
}
__device__ __forceinline__ void cp_commit() {
    asm volatile("cp.async.commit_group;" ::: "memory");
}
__device__ __forceinline__ void cp_wait2() {
    asm volatile("cp.async.wait_group 2;" ::: "memory");
}
__device__ __forceinline__ void ldsm_x4(u32& r0, u32& r1, u32& r2, u32& r3, u32 addr) {
    asm volatile("ldmatrix.sync.aligned.m8n8.x4.shared.b16 {%0,%1,%2,%3}, [%4];"
                 : "=r"(r0), "=r"(r1), "=r"(r2), "=r"(r3) : "r"(addr));
}
__device__ __forceinline__ void mma16816(float* d, const u32* a, u32 b0, u32 b1) {
    asm volatile(
        "mma.sync.aligned.m16n8k16.row.col.f32.bf16.bf16.f32 "
        "{%0,%1,%2,%3}, {%4,%5,%6,%7}, {%8,%9}, {%0,%1,%2,%3};"
        : "+f"(d[0]), "+f"(d[1]), "+f"(d[2]), "+f"(d[3])
        : "r"(a[0]), "r"(a[1]), "r"(a[2]), "r"(a[3]), "r"(b0), "r"(b1));
}
__device__ __forceinline__ void split2(float v, u16& h, u16& l) {
    __nv_bfloat16 hb = __float2bfloat16(v);
    float r = v - __bfloat162float(hb);
    __nv_bfloat16 lb = __float2bfloat16(r);
    h = *reinterpret_cast<u16*>(&hb);
    l = *reinterpret_cast<u16*>(&lb);
}
// swizzled byte offset inside a 128x32 bf16 tile (row stride 64B, 4x16B chunks)
__device__ __forceinline__ u32 swz(int row, int ch) {
    return (u32)(row * 64 + ((ch ^ ((row >> 1) & 3)) << 4));
}

// ---------------- GEMM: D[m,n] = sum_k A[m,k]*B[n,k], bf16 3-product --------
// MODE 0: out = bf16 hi/lo (+bias[n])     MODE 1: out = fp32
#define STAGES 3
#define STAGE_BYTES 32768
#define AHI_OFF 0
#define ALO_OFF 8192
#define BHI_OFF 16384
#define BLO_OFF 24576
#define GEMM_SMEM (STAGES * STAGE_BYTES)

template<int MODE>
__global__ __launch_bounds__(256, 1)
void gemm_mma(const u16* __restrict__ Ahi, const u16* __restrict__ Alo,
              const u16* __restrict__ Bhi, const u16* __restrict__ Blo,
              int K, int lda, int ldb,
              long long strideA, long long strideB,
              float* __restrict__ C, const float* __restrict__ bias,
              u16* __restrict__ Chi, u16* __restrict__ Clo,
              long long ldc, long long strideC)
{
    extern __shared__ char smem[];
    const u32 sb = smem_u32(smem);
    const int tid = threadIdx.x, lane = tid & 31, wid = tid >> 5;
    const int m0 = blockIdx.y * 128, n0 = blockIdx.x * 128, bz = blockIdx.z;

    Ahi += (long long)bz * strideA;  Alo += (long long)bz * strideA;
    Bhi += (long long)bz * strideB;  Blo += (long long)bz * strideB;

    const int KT = K >> 5;  // K / 32, guaranteed >= 3 here

    // per-thread load coords (2 x 16B chunks per buffer per thread)
    const int r0l = tid >> 2,        c0l = tid & 3;        // chunk 0
    const int r1l = (tid + 256) >> 2, c1l = tid & 3;       // chunk 1
    const u32 o0 = swz(r0l, c0l), o1 = swz(r1l, c1l);

    auto load_stage = [&](int kt, int s) {
        const u32 base = sb + s * STAGE_BYTES;
        const int kc = kt * 32;
        {
            const long long ao = (long long)(m0 + r0l) * lda + kc + c0l * 8;
            const long long bo = (long long)(n0 + r0l) * ldb + kc + c0l * 8;
            cp16(base + AHI_OFF + o0, Ahi + ao);
            cp16(base + ALO_OFF + o0, Alo + ao);
            cp16(base + BHI_OFF + o0, Bhi + bo);
            cp16(base + BLO_OFF + o0, Blo + bo);
        }
        {
            const long long ao = (long long)(m0 + r1l) * lda + kc + c1l * 8;
            const long long bo = (long long)(n0 + r1l) * ldb + kc + c1l * 8;
            cp16(base + AHI_OFF + o1, Ahi + ao);
            cp16(base + ALO_OFF + o1, Alo + ao);
            cp16(base + BHI_OFF + o1, Bhi + bo);
            cp16(base + BLO_OFF + o1, Blo + bo);
        }
    };

    float acc[2][8][4];
#pragma unroll
    for (int i = 0; i < 2; ++i)
#pragma unroll
        for (int j = 0; j < 8; ++j)
#pragma unroll
            for (int q = 0; q < 4; ++q) acc[i][j][q] = 0.f;

    const int wm = (wid & 3) * 32;   // warp m offset in tile
    const int wn = (wid >> 2) * 64;  // warp n offset in tile

    // ldmatrix lane addressing (constant per thread)
    const int aRow = (lane & 15);            // + mt*16 + wm
    const int kHi  = (lane >> 4);            // 0/1: low/high 8 of k16
    const int bRow = (lane & 7) + ((lane >> 3) & 1) * 8;  // + nt4*16 + wn

    // prologue
#pragma unroll
    for (int p = 0; p < STAGES; ++p) { load_stage(p, p); cp_commit(); }

    int s = 0;
    for (int kt = 0; kt < KT; ++kt) {
        cp_wait2();
        __syncthreads();
        const u32 base = sb + s * STAGE_BYTES;

#pragma unroll
        for (int k16 = 0; k16 < 2; ++k16) {
            const int kc = k16 * 2 + kHi;
            u32 ah[2][4], al[2][4];
#pragma unroll
            for (int mt = 0; mt < 2; ++mt) {
                const u32 off = swz(wm + mt * 16 + aRow, kc);
                ldsm_x4(ah[mt][0], ah[mt][1], ah[mt][2], ah[mt][3], base + AHI_OFF + off);
                ldsm_x4(al[mt][0], al[mt][1], al[mt][2], al[mt][3], base + ALO_OFF + off);
            }
            u32 bh[8][2], bl[8][2];
#pragma unroll
            for (int nt4 = 0; nt4 < 4; ++nt4) {
                const u32 off = swz(wn + nt4 * 16 + bRow, kc);
                u32 x0, x1, x2, x3;
                ldsm_x4(x0, x1, x2, x3, base + BHI_OFF + off);
                bh[nt4*2][0] = x0; bh[nt4*2][1] = x2;
                bh[nt4*2+1][0] = x1; bh[nt4*2+1][1] = x3;
                ldsm_x4(x0, x1, x2, x3, base + BLO_OFF + off);
                bl[nt4*2][0] = x0; bl[nt4*2][1] = x2;
                bl[nt4*2+1][0] = x1; bl[nt4*2+1][1] = x3;
            }
#pragma unroll
            for (int mt = 0; mt < 2; ++mt)
#pragma unroll
                for (int nt = 0; nt < 8; ++nt) {
                    mma16816(acc[mt][nt], ah[mt], bh[nt][0], bh[nt][1]);
                    mma16816(acc[mt][nt], ah[mt], bl[nt][0], bl[nt][1]);
                    mma16816(acc[mt][nt], al[mt], bh[nt][0], bh[nt][1]);
                }
        }
        __syncthreads();
        if (kt + STAGES < KT) load_stage(kt + STAGES, s);
        cp_commit();  // always commit (possibly empty) to keep group count in sync
        s = (s == STAGES - 1) ? 0 : s + 1;
    }

    // ---- epilogue ----
    const int tq = lane >> 2;        // row within m16 half
    const int tr = (lane & 3) * 2;   // col pair within n8
#pragma unroll
    for (int mt = 0; mt < 2; ++mt) {
#pragma unroll
        for (int nt = 0; nt < 8; ++nt) {
            const int m = m0 + wm + mt * 16 + tq;
            const int n = n0 + wn + nt * 8 + tr;
            const float* a = acc[mt][nt];
            if (MODE == 1) {
                const long long b0 = (long long)bz * strideC + (long long)m * ldc + n;
                const long long b1 = b0 + 8 * ldc;
                *reinterpret_cast<float2*>(C + b0) = make_float2(a[0], a[1]);
                *reinterpret_cast<float2*>(C + b1) = make_float2(a[2], a[3]);
            } else {
                const float bv0 = bias[n], bv1 = bias[n + 1];
                u16 h0, l0, h1, l1;
                const long long b0 = (long long)bz * strideC + (long long)m * ldc + n;
                const long long b1 = b0 + 8 * ldc;
                split2(a[0] + bv0, h0, l0); split2(a[1] + bv1, h1, l1);
                *reinterpret_cast<u32*>(Chi + b0) = (u32)h0 | ((u32)h1 << 16);
                *reinterpret_cast<u32*>(Clo + b0) = (u32)l0 | ((u32)l1 << 16);
                split2(a[2] + bv0, h0, l0); split2(a[3] + bv1, h1, l1);
                *reinterpret_cast<u32*>(Chi + b1) = (u32)h0 | ((u32)h1 << 16);
                *reinterpret_cast<u32*>(Clo + b1) = (u32)l0 | ((u32)l1 << 16);
            }
        }
    }
}

// ---------------- conversion kernels -----------------------------------------
__global__ __launch_bounds__(256)
void split4(const float4* __restrict__ src, uint2* __restrict__ hi, uint2* __restrict__ lo, long long n4)
{
    long long i = (long long)blockIdx.x * 256 + threadIdx.x;
    if (i >= n4) return;
    float4 v = src[i];
    u16 h0,l0,h1,l1,h2,l2,h3,l3;
    split2(v.x,h0,l0); split2(v.y,h1,l1); split2(v.z,h2,l2); split2(v.w,h3,l3);
    hi[i] = make_uint2((u32)h0 | ((u32)h1 << 16), (u32)h2 | ((u32)h3 << 16));
    lo[i] = make_uint2((u32)l0 | ((u32)l1 << 16), (u32)l2 | ((u32)l3 << 16));
}

// X [B][C][N] fp32  ->  XT [B][N][C] bf16 hi/lo
__global__ __launch_bounds__(256)
void transpose_split(const float* __restrict__ X, u16* __restrict__ hi, u16* __restrict__ lo)
{
    __shared__ float tile[32][33];
    const int b  = blockIdx.z;
    const int n0 = blockIdx.x * 32;
    const int c0 = blockIdx.y * 32;
    const int tx = threadIdx.x, ty = threadIdx.y;  // 32 x 8
    const float* src = X + ((long long)b * CIN + c0) * NPIX + n0;
#pragma unroll
    for (int r = 0; r < 32; r += 8)
        tile[ty + r][tx] = src[(long long)(ty + r) * NPIX + tx];
    __syncthreads();
#pragma unroll
    for (int r = 0; r < 32; r += 8) {
        float v = tile[tx][ty + r];
        u16 h, l; split2(v, h, l);
        long long o = ((long long)b * NPIX + n0 + ty + r) * CIN + c0 + tx;
        hi[o] = h; lo[o] = l;
    }
}

// row softmax fp32 -> attn bf16 hi/lo
__global__ __launch_bounds__(256)
void softmax_split(const float* __restrict__ S, u16* __restrict__ hi, u16* __restrict__ lo)
{
    const int PER = NPIX / 256;  // 9
    const long long rb = (long long)blockIdx.x * NPIX;
    const float* p = S + rb;
    const int tid = threadIdx.x;

    float v[PER];
    float mx = -INFINITY;
#pragma unroll
    for (int i = 0; i < PER; ++i) { v[i] = p[tid + i*256]; mx = fmaxf(mx, v[i]); }

    __shared__ float red[8];
#pragma unroll
    for (int o = 16; o; o >>= 1) mx = fmaxf(mx, __shfl_xor_sync(0xffffffffu, mx, o));
    if ((tid & 31) == 0) red[tid >> 5] = mx;
    __syncthreads();
    mx = red[0];
#pragma unroll
    for (int i = 1; i < 8; ++i) mx = fmaxf(mx, red[i]);
    __syncthreads();

    float s = 0.f;
#pragma unroll
    for (int i = 0; i < PER; ++i) { v[i] = __expf(v[i] - mx); s += v[i]; }
#pragma unroll
    for (int o = 16; o; o >>= 1) s += __shfl_xor_sync(0xffffffffu, s, o);
    if ((tid & 31) == 0) red[tid >> 5] = s;
    __syncthreads();
    s = red[0];
#pragma unroll
    for (int i = 1; i < 8; ++i) s += red[i];

    const float inv = 1.f / s;
#pragma unroll
    for (int i = 0; i < PER; ++i) {
        u16 h, l; split2(v[i] * inv, h, l);
        hi[rb + tid + i*256] = h;
        lo[rb + tid + i*256] = l;
    }
}

__global__ __launch_bounds__(256)
void copy_features(const float* __restrict__ src, float* __restrict__ dst)
{
    const long long perBatch4 = (long long)CIN * NPIX / 4;
    const long long total4 = (long long)BATCH * perBatch4;
    long long idx = (long long)blockIdx.x * blockDim.x + threadIdx.x;
    if (idx >= total4) return;
    long long b = idx / perBatch4;
    long long r = idx % perBatch4;
    reinterpret_cast<float4*>(dst)[b * ((long long)2 * CIN * NPIX / 4) + r] =
        reinterpret_cast<const float4*>(src)[idx];
}

// ---------------- host --------------------------------------------------------
extern "C" void kernel_launch(void* const* d_in, const int* in_sizes, int n_in,
                              void* d_out, int out_size)
{
    const float* left  = (const float*)d_in[0];
    const float* right = (const float*)d_in[1];
    const float* wq    = (const float*)d_in[2];
    const float* bq    = (const float*)d_in[3];
    const float* wr    = (const float*)d_in[4];
    const float* br    = (const float*)d_in[5];
    float* out = (float*)d_out;

    void *fLhi, *fLlo, *fRhi, *fRlo, *fTLhi, *fTLlo, *fTRhi, *fTRlo;
    void *wqhi, *wqlo, *wrhi, *wrlo;
    void *QLhi, *QLlo, *KRhi, *KRlo, *QRhi, *QRlo, *KLhi, *KLlo;
    void *Sraw, *Ahi_, *Alo_;
    cudaGetSymbolAddress(&fLhi, g_fLhi);   cudaGetSymbolAddress(&fLlo, g_fLlo);
    cudaGetSymbolAddress(&fRhi, g_fRhi);   cudaGetSymbolAddress(&fRlo, g_fRlo);
    cudaGetSymbolAddress(&fTLhi, g_fTLhi); cudaGetSymbolAddress(&fTLlo, g_fTLlo);
    cudaGetSymbolAddress(&fTRhi, g_fTRhi); cudaGetSymbolAddress(&fTRlo, g_fTRlo);
    cudaGetSymbolAddress(&wqhi, g_wqhi);   cudaGetSymbolAddress(&wqlo, g_wqlo);
    cudaGetSymbolAddress(&wrhi, g_wrhi);   cudaGetSymbolAddress(&wrlo, g_wrlo);
    cudaGetSymbolAddress(&QLhi, g_QLhi);   cudaGetSymbolAddress(&QLlo, g_QLlo);
    cudaGetSymbolAddress(&KRhi, g_KRhi);   cudaGetSymbolAddress(&KRlo, g_KRlo);
    cudaGetSymbolAddress(&QRhi, g_QRhi);   cudaGetSymbolAddress(&QRlo, g_QRlo);
    cudaGetSymbolAddress(&KLhi, g_KLhi);   cudaGetSymbolAddress(&KLlo, g_KLlo);
    cudaGetSymbolAddress(&Sraw, g_S);
    cudaGetSymbolAddress(&Ahi_, g_Ahi);    cudaGetSymbolAddress(&Alo_, g_Alo);
    float* S = (float*)Sraw;

    cudaFuncSetAttribute(gemm_mma<0>, cudaFuncAttributeMaxDynamicSharedMemorySize, GEMM_SMEM);
    cudaFuncSetAttribute(gemm_mma<1>, cudaFuncAttributeMaxDynamicSharedMemorySize, GEMM_SMEM);

    // ---- conversions ----
    {
        long long nW4 = (long long)DHID * CIN / 4;
        split4<<<(unsigned)((nW4 + 255) / 256), 256>>>((const float4*)wq, (uint2*)wqhi, (uint2*)wqlo, nW4);
        split4<<<(unsigned)((nW4 + 255) / 256), 256>>>((const float4*)wr, (uint2*)wrhi, (uint2*)wrlo, nW4);
        long long nF4 = (long long)BATCH * CIN * NPIX / 4;
        split4<<<(unsigned)((nF4 + 255) / 256), 256>>>((const float4*)left,  (uint2*)fLhi, (uint2*)fLlo, nF4);
        split4<<<(unsigned)((nF4 + 255) / 256), 256>>>((const float4*)right, (uint2*)fRhi, (uint2*)fRlo, nF4);
        dim3 tg(NPIX / 32, CIN / 32, BATCH);
        transpose_split<<<tg, dim3(32, 8)>>>(left,  (u16*)fTLhi, (u16*)fTLlo);
        transpose_split<<<tg, dim3(32, 8)>>>(right, (u16*)fTRhi, (u16*)fTRlo);
    }

    const long long featStride = (long long)CIN * NPIX;
    const long long qkStride   = (long long)NPIX * DHID;
    const long long sStride    = (long long)NPIX * NPIX;
    const long long outStride  = 2LL * CIN * NPIX;
    float* outL = out;
    float* outR = out + (long long)BATCH * outStride;

    // ---- projections (MODE 0): Q[b,n,d] = featT[b,n,:] . W[d,:] + bias ----
    {
        dim3 grid(DHID / 128, NPIX / 128, BATCH);  // 2 x 18 x 4
        struct { void *ah, *al, *bh, *bl; const float* bias; void *ch, *cl; } cfg[4] = {
            {fTLhi, fTLlo, wqhi, wqlo, bq, QLhi, QLlo},
            {fTRhi, fTRlo, wrhi, wrlo, br, KRhi, KRlo},
            {fTRhi, fTRlo, wqhi, wqlo, bq, QRhi, QRlo},
            {fTLhi, fTLlo, wrhi, wrlo, br, KLhi, KLlo},
        };
        for (int i = 0; i < 4; ++i) {
            gemm_mma<0><<<grid, 256, GEMM_SMEM>>>(
                (const u16*)cfg[i].ah, (const u16*)cfg[i].al,
                (const u16*)cfg[i].bh, (const u16*)cfg[i].bl,
                CIN, CIN, CIN, (long long)NPIX * CIN, 0LL,
                nullptr, cfg[i].bias, (u16*)cfg[i].ch, (u16*)cfg[i].cl,
                (long long)DHID, qkStride);
        }
    }

    // ---- per-direction: scores -> softmax -> attn.V ----
    dim3 scoreGrid(NPIX / 128, NPIX / 128, BATCH);  // 18 x 18 x 4
    dim3 avGrid(NPIX / 128, CIN / 128, BATCH);      // 18 x 16 x 4

    for (int dir = 0; dir < 2; ++dir) {
        void* Qh = dir == 0 ? QLhi : QRhi;  void* Ql = dir == 0 ? QLlo : QRlo;
        void* Kh = dir == 0 ? KRhi : KLhi;  void* Kl = dir == 0 ? KRlo : KLlo;
        void* Vh = dir == 0 ? fRhi : fLhi;  void* Vl = dir == 0 ? fRlo : fLlo;
        float* Cout = (dir == 0 ? outL : outR) + (long long)CIN * NPIX;

        // scores[n,m] = Q[n,:].K[m,:]
        gemm_mma<1><<<scoreGrid, 256, GEMM_SMEM>>>(
            (const u16*)Qh, (const u16*)Ql, (const u16*)Kh, (const u16*)Kl,
            DHID, DHID, DHID, qkStride, qkStride,
            S, nullptr, nullptr, nullptr, (long long)NPIX, sStride);

        softmax_split<<<BATCH * NPIX, 256>>>(S, (u16*)Ahi_, (u16*)Alo_);

        // out[c,n] = sum_m V[c,m] * attn[n,m]
        gemm_mma<1><<<avGrid, 256, GEMM_SMEM>>>(
            (const u16*)Vh, (const u16*)Vl, (const u16*)Ahi_, (const u16*)Alo_,
            NPIX, NPIX, NPIX, featStride, sStride,
            Cout, nullptr, nullptr, nullptr, (long long)NPIX, outStride);
    }

    // ---- raw feature passthrough ----
    const int copyBlocks = (int)(((long long)BATCH * CIN * NPIX / 4 + 255) / 256);
    copy_features<<<copyBlocks, 256>>>(left,  outL);
    copy_features<<<copyBlocks, 256>>>(right, outR);
}

// round 4
// speedup vs baseline: 2.9682x; 1.2849x over previous
#include <cuda_runtime.h>
#include <cuda_bf16.h>
#include <cuda_fp16.h>
#include <math.h>
#include <stdint.h>

typedef unsigned short u16;
typedef unsigned int   u32;
typedef unsigned long long u64;

#define BATCH 4
#define CIN   2048
#define NPIX  2304
#define DHID  256

// ---------------- scratch (static device globals; no allocations) ----------
__device__ u16 g_fLhi[(size_t)BATCH*CIN*NPIX];   // left features fp16 hi, [B][C][N] (V operand)
__device__ u16 g_fLlo[(size_t)BATCH*CIN*NPIX];   // fp16 lo
__device__ u16 g_fRhi[(size_t)BATCH*CIN*NPIX];
__device__ u16 g_fRlo[(size_t)BATCH*CIN*NPIX];
__device__ u16 g_fTLhi[(size_t)BATCH*NPIX*CIN];  // transposed [B][N][C] bf16 hi/lo (proj operand)
__device__ u16 g_fTLlo[(size_t)BATCH*NPIX*CIN];
__device__ u16 g_fTRhi[(size_t)BATCH*NPIX*CIN];
__device__ u16 g_fTRlo[(size_t)BATCH*NPIX*CIN];
__device__ u16 g_wqhi[(size_t)DHID*CIN];
__device__ u16 g_wqlo[(size_t)DHID*CIN];
__device__ u16 g_wrhi[(size_t)DHID*CIN];
__device__ u16 g_wrlo[(size_t)DHID*CIN];
__device__ u16 g_QLhi[(size_t)BATCH*NPIX*DHID];
__device__ u16 g_QLlo[(size_t)BATCH*NPIX*DHID];
__device__ u16 g_KRhi[(size_t)BATCH*NPIX*DHID];
__device__ u16 g_KRlo[(size_t)BATCH*NPIX*DHID];
__device__ u16 g_QRhi[(size_t)BATCH*NPIX*DHID];
__device__ u16 g_QRlo[(size_t)BATCH*NPIX*DHID];
__device__ u16 g_KLhi[(size_t)BATCH*NPIX*DHID];
__device__ u16 g_KLlo[(size_t)BATCH*NPIX*DHID];
__device__ float g_S[(size_t)BATCH*NPIX*NPIX];   // fp32 scores
__device__ u16 g_A16[(size_t)BATCH*NPIX*NPIX];   // attn fp16 (single)

// ---------------- helpers ----------------------------------------------------
__device__ __forceinline__ u32 smem_u32(const void* p) {
    u32 a;
    asm("{ .reg .u64 t; cvta.to.shared.u64 t, %1; cvt.u32.u64 %0, t; }" : "=r"(a) : "l"(p));
    return a;
}
__device__ __forceinline__ void cp16(u32 dst, const void* src) {
    asm volatile("cp.async.cg.shared.global [%0], [%1], 16;" :: "r"(dst), "l"(src));
}
__device__ __forceinline__ void cp_commit() {
    asm volatile("cp.async.commit_group;" ::: "memory");
}
__device__ __forceinline__ void cp_wait2() {
    asm volatile("cp.async.wait_group 2;" ::: "memory");
}
__device__ __forceinline__ void cp_wait3() {
    asm volatile("cp.async.wait_group 3;" ::: "memory");
}
__device__ __forceinline__ void ldsm_x4(u32& r0, u32& r1, u32& r2, u32& r3, u32 addr) {
    asm volatile("ldmatrix.sync.aligned.m8n8.x4.shared.b16 {%0,%1,%2,%3}, [%4];"
                 : "=r"(r0), "=r"(r1), "=r"(r2), "=r"(r3) : "r"(addr));
}
__device__ __forceinline__ void mma_bf16(float* d, const u32* a, u32 b0, u32 b1) {
    asm volatile(
        "mma.sync.aligned.m16n8k16.row.col.f32.bf16.bf16.f32 "
        "{%0,%1,%2,%3}, {%4,%5,%6,%7}, {%8,%9}, {%0,%1,%2,%3};"
        : "+f"(d[0]), "+f"(d[1]), "+f"(d[2]), "+f"(d[3])
        : "r"(a[0]), "r"(a[1]), "r"(a[2]), "r"(a[3]), "r"(b0), "r"(b1));
}
__device__ __forceinline__ void mma_f16(float* d, const u32* a, u32 b0, u32 b1) {
    asm volatile(
        "mma.sync.aligned.m16n8k16.row.col.f32.f16.f16.f32 "
        "{%0,%1,%2,%3}, {%4,%5,%6,%7}, {%8,%9}, {%0,%1,%2,%3};"
        : "+f"(d[0]), "+f"(d[1]), "+f"(d[2]), "+f"(d[3])
        : "r"(a[0]), "r"(a[1]), "r"(a[2]), "r"(a[3]), "r"(b0), "r"(b1));
}
__device__ __forceinline__ void split2(float v, u16& h, u16& l) {   // bf16 split
    __nv_bfloat16 hb = __float2bfloat16(v);
    float r = v - __bfloat162float(hb);
    __nv_bfloat16 lb = __float2bfloat16(r);
    h = *reinterpret_cast<u16*>(&hb);
    l = *reinterpret_cast<u16*>(&lb);
}
__device__ __forceinline__ void split2h(float v, u16& h, u16& l) {  // fp16 split
    __half hb = __float2half_rn(v);
    float r = v - __half2float(hb);
    __half lb = __float2half_rn(r);
    h = *reinterpret_cast<u16*>(&hb);
    l = *reinterpret_cast<u16*>(&lb);
}
// swizzled byte offset inside a 128x32 16-bit tile (row stride 64B, 4x16B chunks)
__device__ __forceinline__ u32 swz(int row, int ch) {
    return (u32)(row * 64 + ((ch ^ ((row >> 1) & 3)) << 4));
}

// ============================================================================
// GEMM A: bf16 3-product (hi*hi + hi*lo + lo*hi), CTA 128x128x32, 3 stages.
// MODE 0: out = bf16 hi/lo (+bias[n])     MODE 1: out = fp32
// ============================================================================
#define STAGES 3
#define STAGE_BYTES 32768
#define AHI_OFF 0
#define ALO_OFF 8192
#define BHI_OFF 16384
#define BLO_OFF 24576
#define GEMM_SMEM (STAGES * STAGE_BYTES)

template<int MODE>
__global__ __launch_bounds__(256, 1)
void gemm_mma(const u16* __restrict__ Ahi, const u16* __restrict__ Alo,
              const u16* __restrict__ Bhi, const u16* __restrict__ Blo,
              int K, int lda, int ldb,
              long long strideA, long long strideB,
              float* __restrict__ C, const float* __restrict__ bias,
              u16* __restrict__ Chi, u16* __restrict__ Clo,
              long long ldc, long long strideC)
{
    extern __shared__ char smem[];
    const u32 sb = smem_u32(smem);
    const int tid = threadIdx.x, lane = tid & 31, wid = tid >> 5;
    const int m0 = blockIdx.y * 128, n0 = blockIdx.x * 128, bz = blockIdx.z;

    Ahi += (long long)bz * strideA;  Alo += (long long)bz * strideA;
    Bhi += (long long)bz * strideB;  Blo += (long long)bz * strideB;

    const int KT = K >> 5;

    const int r0l = tid >> 2,         c0l = tid & 3;
    const int r1l = (tid + 256) >> 2, c1l = tid & 3;
    const u32 o0 = swz(r0l, c0l), o1 = swz(r1l, c1l);

    auto load_stage = [&](int kt, int s) {
        const u32 base = sb + s * STAGE_BYTES;
        const int kc = kt * 32;
        {
            const long long ao = (long long)(m0 + r0l) * lda + kc + c0l * 8;
            const long long bo = (long long)(n0 + r0l) * ldb + kc + c0l * 8;
            cp16(base + AHI_OFF + o0, Ahi + ao);
            cp16(base + ALO_OFF + o0, Alo + ao);
            cp16(base + BHI_OFF + o0, Bhi + bo);
            cp16(base + BLO_OFF + o0, Blo + bo);
        }
        {
            const long long ao = (long long)(m0 + r1l) * lda + kc + c1l * 8;
            const long long bo = (long long)(n0 + r1l) * ldb + kc + c1l * 8;
            cp16(base + AHI_OFF + o1, Ahi + ao);
            cp16(base + ALO_OFF + o1, Alo + ao);
            cp16(base + BHI_OFF + o1, Bhi + bo);
            cp16(base + BLO_OFF + o1, Blo + bo);
        }
    };

    float acc[2][8][4];
#pragma unroll
    for (int i = 0; i < 2; ++i)
#pragma unroll
        for (int j = 0; j < 8; ++j)
#pragma unroll
            for (int q = 0; q < 4; ++q) acc[i][j][q] = 0.f;

    const int wm = (wid & 3) * 32;
    const int wn = (wid >> 2) * 64;
    const int aRow = (lane & 15);
    const int kHi  = (lane >> 4);
    const int bRow = (lane & 7) + ((lane >> 3) & 1) * 8;

#pragma unroll
    for (int p = 0; p < STAGES; ++p) { load_stage(p, p); cp_commit(); }

    int s = 0;
    for (int kt = 0; kt < KT; ++kt) {
        cp_wait2();
        __syncthreads();
        const u32 base = sb + s * STAGE_BYTES;

#pragma unroll
        for (int k16 = 0; k16 < 2; ++k16) {
            const int kc = k16 * 2 + kHi;
            u32 ah[2][4], al[2][4];
#pragma unroll
            for (int mt = 0; mt < 2; ++mt) {
                const u32 off = swz(wm + mt * 16 + aRow, kc);
                ldsm_x4(ah[mt][0], ah[mt][1], ah[mt][2], ah[mt][3], base + AHI_OFF + off);
                ldsm_x4(al[mt][0], al[mt][1], al[mt][2], al[mt][3], base + ALO_OFF + off);
            }
            u32 bh[8][2], bl[8][2];
#pragma unroll
            for (int nt4 = 0; nt4 < 4; ++nt4) {
                const u32 off = swz(wn + nt4 * 16 + bRow, kc);
                u32 x0, x1, x2, x3;
                ldsm_x4(x0, x1, x2, x3, base + BHI_OFF + off);
                bh[nt4*2][0] = x0; bh[nt4*2][1] = x2;
                bh[nt4*2+1][0] = x1; bh[nt4*2+1][1] = x3;
                ldsm_x4(x0, x1, x2, x3, base + BLO_OFF + off);
                bl[nt4*2][0] = x0; bl[nt4*2][1] = x2;
                bl[nt4*2+1][0] = x1; bl[nt4*2+1][1] = x3;
            }
#pragma unroll
            for (int mt = 0; mt < 2; ++mt)
#pragma unroll
                for (int nt = 0; nt < 8; ++nt) {
                    mma_bf16(acc[mt][nt], ah[mt], bh[nt][0], bh[nt][1]);
                    mma_bf16(acc[mt][nt], ah[mt], bl[nt][0], bl[nt][1]);
                    mma_bf16(acc[mt][nt], al[mt], bh[nt][0], bh[nt][1]);
                }
        }
        __syncthreads();
        if (kt + STAGES < KT) load_stage(kt + STAGES, s);
        cp_commit();
        s = (s == STAGES - 1) ? 0 : s + 1;
    }

    const int tq = lane >> 2;
    const int tr = (lane & 3) * 2;
#pragma unroll
    for (int mt = 0; mt < 2; ++mt) {
#pragma unroll
        for (int nt = 0; nt < 8; ++nt) {
            const int m = m0 + wm + mt * 16 + tq;
            const int n = n0 + wn + nt * 8 + tr;
            const float* a = acc[mt][nt];
            const long long b0 = (long long)bz * strideC + (long long)m * ldc + n;
            const long long b1 = b0 + 8 * ldc;
            if (MODE == 1) {
                *reinterpret_cast<float2*>(C + b0) = make_float2(a[0], a[1]);
                *reinterpret_cast<float2*>(C + b1) = make_float2(a[2], a[3]);
            } else {
                const float bv0 = bias[n], bv1 = bias[n + 1];
                u16 h0, l0, h1, l1;
                split2(a[0] + bv0, h0, l0); split2(a[1] + bv1, h1, l1);
                *reinterpret_cast<u32*>(Chi + b0) = (u32)h0 | ((u32)h1 << 16);
                *reinterpret_cast<u32*>(Clo + b0) = (u32)l0 | ((u32)l1 << 16);
                split2(a[2] + bv0, h0, l0); split2(a[3] + bv1, h1, l1);
                *reinterpret_cast<u32*>(Chi + b1) = (u32)h0 | ((u32)h1 << 16);
                *reinterpret_cast<u32*>(Clo + b1) = (u32)l0 | ((u32)l1 << 16);
            }
        }
    }
}

// ============================================================================
// GEMM B (attn.V): fp16 2-product — A = V hi/lo, B = attn single fp16.
// out[m,n] = sum_k (Ahi+Alo)[m,k] * B[n,k], fp32 out. CTA 128x128x32, 4 stages.
// ============================================================================
#define AV_STAGES 4
#define AV_STAGE_BYTES 24576
#define AV_AHI 0
#define AV_ALO 8192
#define AV_B   16384
#define AV_SMEM (AV_STAGES * AV_STAGE_BYTES)

__global__ __launch_bounds__(256, 1)
void gemm_av(const u16* __restrict__ Ahi, const u16* __restrict__ Alo,
             const u16* __restrict__ B,
             int K, int lda, int ldb,
             long long strideA, long long strideB,
             float* __restrict__ C, long long ldc, long long strideC)
{
    extern __shared__ char smem[];
    const u32 sb = smem_u32(smem);
    const int tid = threadIdx.x, lane = tid & 31, wid = tid >> 5;
    const int m0 = blockIdx.y * 128, n0 = blockIdx.x * 128, bz = blockIdx.z;

    Ahi += (long long)bz * strideA;  Alo += (long long)bz * strideA;
    B   += (long long)bz * strideB;

    const int KT = K >> 5;  // 72

    const int r0l = tid >> 2,         c0l = tid & 3;
    const int r1l = (tid + 256) >> 2, c1l = tid & 3;
    const u32 o0 = swz(r0l, c0l), o1 = swz(r1l, c1l);

    auto load_stage = [&](int kt, int s) {
        const u32 base = sb + s * AV_STAGE_BYTES;
        const int kc = kt * 32;
        {
            const long long ao = (long long)(m0 + r0l) * lda + kc + c0l * 8;
            const long long bo = (long long)(n0 + r0l) * ldb + kc + c0l * 8;
            cp16(base + AV_AHI + o0, Ahi + ao);
            cp16(base + AV_ALO + o0, Alo + ao);
            cp16(base + AV_B   + o0, B + bo);
        }
        {
            const long long ao = (long long)(m0 + r1l) * lda + kc + c1l * 8;
            const long long bo = (long long)(n0 + r1l) * ldb + kc + c1l * 8;
            cp16(base + AV_AHI + o1, Ahi + ao);
            cp16(base + AV_ALO + o1, Alo + ao);
            cp16(base + AV_B   + o1, B + bo);
        }
    };

    float acc[2][8][4];
#pragma unroll
    for (int i = 0; i < 2; ++i)
#pragma unroll
        for (int j = 0; j < 8; ++j)
#pragma unroll
            for (int q = 0; q < 4; ++q) acc[i][j][q] = 0.f;

    const int wm = (wid & 3) * 32;
    const int wn = (wid >> 2) * 64;
    const int aRow = (lane & 15);
    const int kHi  = (lane >> 4);
    const int bRow = (lane & 7) + ((lane >> 3) & 1) * 8;

#pragma unroll
    for (int p = 0; p < AV_STAGES; ++p) { load_stage(p, p); cp_commit(); }

    int s = 0;
    for (int kt = 0; kt < KT; ++kt) {
        cp_wait3();
        __syncthreads();
        const u32 base = sb + s * AV_STAGE_BYTES;

#pragma unroll
        for (int k16 = 0; k16 < 2; ++k16) {
            const int kc = k16 * 2 + kHi;
            u32 ah[2][4], al[2][4];
#pragma unroll
            for (int mt = 0; mt < 2; ++mt) {
                const u32 off = swz(wm + mt * 16 + aRow, kc);
                ldsm_x4(ah[mt][0], ah[mt][1], ah[mt][2], ah[mt][3], base + AV_AHI + off);
                ldsm_x4(al[mt][0], al[mt][1], al[mt][2], al[mt][3], base + AV_ALO + off);
            }
            u32 bb[8][2];
#pragma unroll
            for (int nt4 = 0; nt4 < 4; ++nt4) {
                const u32 off = swz(wn + nt4 * 16 + bRow, kc);
                u32 x0, x1, x2, x3;
                ldsm_x4(x0, x1, x2, x3, base + AV_B + off);
                bb[nt4*2][0] = x0; bb[nt4*2][1] = x2;
                bb[nt4*2+1][0] = x1; bb[nt4*2+1][1] = x3;
            }
#pragma unroll
            for (int mt = 0; mt < 2; ++mt)
#pragma unroll
                for (int nt = 0; nt < 8; ++nt) {
                    mma_f16(acc[mt][nt], ah[mt], bb[nt][0], bb[nt][1]);
                    mma_f16(acc[mt][nt], al[mt], bb[nt][0], bb[nt][1]);
                }
        }
        __syncthreads();
        if (kt + AV_STAGES < KT) load_stage(kt + AV_STAGES, s);
        cp_commit();
        s = (s == AV_STAGES - 1) ? 0 : s + 1;
    }

    const int tq = lane >> 2;
    const int tr = (lane & 3) * 2;
#pragma unroll
    for (int mt = 0; mt < 2; ++mt) {
#pragma unroll
        for (int nt = 0; nt < 8; ++nt) {
            const int m = m0 + wm + mt * 16 + tq;
            const int n = n0 + wn + nt * 8 + tr;
            const float* a = acc[mt][nt];
            const long long b0 = (long long)bz * strideC + (long long)m * ldc + n;
            const long long b1 = b0 + 8 * ldc;
            *reinterpret_cast<float2*>(C + b0) = make_float2(a[0], a[1]);
            *reinterpret_cast<float2*>(C + b1) = make_float2(a[2], a[3]);
        }
    }
}

// ---------------- conversion kernels -----------------------------------------
// fp32 -> fp16 hi/lo (for V operands)
__global__ __launch_bounds__(256)
void split4h(const float4* __restrict__ src, uint2* __restrict__ hi, uint2* __restrict__ lo, long long n4)
{
    long long i = (long long)blockIdx.x * 256 + threadIdx.x;
    if (i >= n4) return;
    float4 v = src[i];
    u16 h0,l0,h1,l1,h2,l2,h3,l3;
    split2h(v.x,h0,l0); split2h(v.y,h1,l1); split2h(v.z,h2,l2); split2h(v.w,h3,l3);
    hi[i] = make_uint2((u32)h0 | ((u32)h1 << 16), (u32)h2 | ((u32)h3 << 16));
    lo[i] = make_uint2((u32)l0 | ((u32)l1 << 16), (u32)l2 | ((u32)l3 << 16));
}
// fp32 -> bf16 hi/lo (for weights)
__global__ __launch_bounds__(256)
void split4(const float4* __restrict__ src, uint2* __restrict__ hi, uint2* __restrict__ lo, long long n4)
{
    long long i = (long long)blockIdx.x * 256 + threadIdx.x;
    if (i >= n4) return;
    float4 v = src[i];
    u16 h0,l0,h1,l1,h2,l2,h3,l3;
    split2(v.x,h0,l0); split2(v.y,h1,l1); split2(v.z,h2,l2); split2(v.w,h3,l3);
    hi[i] = make_uint2((u32)h0 | ((u32)h1 << 16), (u32)h2 | ((u32)h3 << 16));
    lo[i] = make_uint2((u32)l0 | ((u32)l1 << 16), (u32)l2 | ((u32)l3 << 16));
}

// X [B][C][N] fp32 -> XT [B][N][C] bf16 hi/lo
__global__ __launch_bounds__(256)
void transpose_split(const float* __restrict__ X, u16* __restrict__ hi, u16* __restrict__ lo)
{
    __shared__ float tile[32][33];
    const int b  = blockIdx.z;
    const int n0 = blockIdx.x * 32;
    const int c0 = blockIdx.y * 32;
    const int tx = threadIdx.x, ty = threadIdx.y;
    const float* src = X + ((long long)b * CIN + c0) * NPIX + n0;
#pragma unroll
    for (int r = 0; r < 32; r += 8)
        tile[ty + r][tx] = src[(long long)(ty + r) * NPIX + tx];
    __syncthreads();
#pragma unroll
    for (int r = 0; r < 32; r += 8) {
        float v = tile[tx][ty + r];
        u16 h, l; split2(v, h, l);
        long long o = ((long long)b * NPIX + n0 + ty + r) * CIN + c0 + tx;
        hi[o] = h; lo[o] = l;
    }
}

// row softmax fp32 -> attn fp16 single
__global__ __launch_bounds__(256)
void softmax_h(const float* __restrict__ S, u16* __restrict__ A)
{
    const int PER = NPIX / 256;  // 9
    const long long rb = (long long)blockIdx.x * NPIX;
    const float* p = S + rb;
    const int tid = threadIdx.x;

    float v[PER];
    float mx = -INFINITY;
#pragma unroll
    for (int i = 0; i < PER; ++i) { v[i] = p[tid + i*256]; mx = fmaxf(mx, v[i]); }

    __shared__ float red[8];
#pragma unroll
    for (int o = 16; o; o >>= 1) mx = fmaxf(mx, __shfl_xor_sync(0xffffffffu, mx, o));
    if ((tid & 31) == 0) red[tid >> 5] = mx;
    __syncthreads();
    mx = red[0];
#pragma unroll
    for (int i = 1; i < 8; ++i) mx = fmaxf(mx, red[i]);
    __syncthreads();

    float s = 0.f;
#pragma unroll
    for (int i = 0; i < PER; ++i) { v[i] = __expf(v[i] - mx); s += v[i]; }
#pragma unroll
    for (int o = 16; o; o >>= 1) s += __shfl_xor_sync(0xffffffffu, s, o);
    if ((tid & 31) == 0) red[tid >> 5] = s;
    __syncthreads();
    s = red[0];
#pragma unroll
    for (int i = 1; i < 8; ++i) s += red[i];

    const float inv = 1.f / s;
#pragma unroll
    for (int i = 0; i < PER; ++i) {
        __half h = __float2half_rn(v[i] * inv);
        A[rb + tid + i*256] = *reinterpret_cast<u16*>(&h);
    }
}

__global__ __launch_bounds__(256)
void copy_features(const float* __restrict__ src, float* __restrict__ dst)
{
    const long long perBatch4 = (long long)CIN * NPIX / 4;
    const long long total4 = (long long)BATCH * perBatch4;
    long long idx = (long long)blockIdx.x * blockDim.x + threadIdx.x;
    if (idx >= total4) return;
    long long b = idx / perBatch4;
    long long r = idx % perBatch4;
    reinterpret_cast<float4*>(dst)[b * ((long long)2 * CIN * NPIX / 4) + r] =
        reinterpret_cast<const float4*>(src)[idx];
}

// ---------------- host --------------------------------------------------------
extern "C" void kernel_launch(void* const* d_in, const int* in_sizes, int n_in,
                              void* d_out, int out_size)
{
    const float* left  = (const float*)d_in[0];
    const float* right = (const float*)d_in[1];
    const float* wq    = (const float*)d_in[2];
    const float* bq    = (const float*)d_in[3];
    const float* wr    = (const float*)d_in[4];
    const float* br    = (const float*)d_in[5];
    float* out = (float*)d_out;

    void *fLhi, *fLlo, *fRhi, *fRlo, *fTLhi, *fTLlo, *fTRhi, *fTRlo;
    void *wqhi, *wqlo, *wrhi, *wrlo;
    void *QLhi, *QLlo, *KRhi, *KRlo, *QRhi, *QRlo, *KLhi, *KLlo;
    void *Sraw, *A16;
    cudaGetSymbolAddress(&fLhi, g_fLhi);   cudaGetSymbolAddress(&fLlo, g_fLlo);
    cudaGetSymbolAddress(&fRhi, g_fRhi);   cudaGetSymbolAddress(&fRlo, g_fRlo);
    cudaGetSymbolAddress(&fTLhi, g_fTLhi); cudaGetSymbolAddress(&fTLlo, g_fTLlo);
    cudaGetSymbolAddress(&fTRhi, g_fTRhi); cudaGetSymbolAddress(&fTRlo, g_fTRlo);
    cudaGetSymbolAddress(&wqhi, g_wqhi);   cudaGetSymbolAddress(&wqlo, g_wqlo);
    cudaGetSymbolAddress(&wrhi, g_wrhi);   cudaGetSymbolAddress(&wrlo, g_wrlo);
    cudaGetSymbolAddress(&QLhi, g_QLhi);   cudaGetSymbolAddress(&QLlo, g_QLlo);
    cudaGetSymbolAddress(&KRhi, g_KRhi);   cudaGetSymbolAddress(&KRlo, g_KRlo);
    cudaGetSymbolAddress(&QRhi, g_QRhi);   cudaGetSymbolAddress(&QRlo, g_QRlo);
    cudaGetSymbolAddress(&KLhi, g_KLhi);   cudaGetSymbolAddress(&KLlo, g_KLlo);
    cudaGetSymbolAddress(&Sraw, g_S);
    cudaGetSymbolAddress(&A16, g_A16);
    float* S = (float*)Sraw;

    cudaFuncSetAttribute(gemm_mma<0>, cudaFuncAttributeMaxDynamicSharedMemorySize, GEMM_SMEM);
    cudaFuncSetAttribute(gemm_mma<1>, cudaFuncAttributeMaxDynamicSharedMemorySize, GEMM_SMEM);
    cudaFuncSetAttribute(gemm_av, cudaFuncAttributeMaxDynamicSharedMemorySize, AV_SMEM);

    // ---- conversions ----
    {
        long long nW4 = (long long)DHID * CIN / 4;
        split4<<<(unsigned)((nW4 + 255) / 256), 256>>>((const float4*)wq, (uint2*)wqhi, (uint2*)wqlo, nW4);
        split4<<<(unsigned)((nW4 + 255) / 256), 256>>>((const float4*)wr, (uint2*)wrhi, (uint2*)wrlo, nW4);
        long long nF4 = (long long)BATCH * CIN * NPIX / 4;
        split4h<<<(unsigned)((nF4 + 255) / 256), 256>>>((const float4*)left,  (uint2*)fLhi, (uint2*)fLlo, nF4);
        split4h<<<(unsigned)((nF4 + 255) / 256), 256>>>((const float4*)right, (uint2*)fRhi, (uint2*)fRlo, nF4);
        dim3 tg(NPIX / 32, CIN / 32, BATCH);
        transpose_split<<<tg, dim3(32, 8)>>>(left,  (u16*)fTLhi, (u16*)fTLlo);
        transpose_split<<<tg, dim3(32, 8)>>>(right, (u16*)fTRhi, (u16*)fTRlo);
    }

    const long long featStride = (long long)CIN * NPIX;
    const long long qkStride   = (long long)NPIX * DHID;
    const long long sStride    = (long long)NPIX * NPIX;
    const long long outStride  = 2LL * CIN * NPIX;
    float* outL = out;
    float* outR = out + (long long)BATCH * outStride;

    // ---- projections (bf16 3-product): Q[b,n,d] = featT[b,n,:] . W[d,:] + bias ----
    {
        dim3 grid(DHID / 128, NPIX / 128, BATCH);
        struct { void *ah, *al, *bh, *bl; const float* bias; void *ch, *cl; } cfg[4] = {
            {fTLhi, fTLlo, wqhi, wqlo, bq, QLhi, QLlo},
            {fTRhi, fTRlo, wrhi, wrlo, br, KRhi, KRlo},
            {fTRhi, fTRlo, wqhi, wqlo, bq, QRhi, QRlo},
            {fTLhi, fTLlo, wrhi, wrlo, br, KLhi, KLlo},
        };
        for (int i = 0; i < 4; ++i) {
            gemm_mma<0><<<grid, 256, GEMM_SMEM>>>(
                (const u16*)cfg[i].ah, (const u16*)cfg[i].al,
                (const u16*)cfg[i].bh, (const u16*)cfg[i].bl,
                CIN, CIN, CIN, (long long)NPIX * CIN, 0LL,
                nullptr, cfg[i].bias, (u16*)cfg[i].ch, (u16*)cfg[i].cl,
                (long long)DHID, qkStride);
        }
    }

    dim3 scoreGrid(NPIX / 128, NPIX / 128, BATCH);
    dim3 avGrid(NPIX / 128, CIN / 128, BATCH);

    for (int dir = 0; dir < 2; ++dir) {
        void* Qh = dir == 0 ? QLhi : QRhi;  void* Ql = dir == 0 ? QLlo : QRlo;
        void* Kh = dir == 0 ? KRhi : KLhi;  void* Kl = dir == 0 ? KRlo : KLlo;
        void* Vh = dir == 0 ? fRhi : fLhi;  void* Vl = dir == 0 ? fRlo : fLlo;
        float* Cout = (dir == 0 ? outL : outR) + (long long)CIN * NPIX;

        // scores[n,m] = Q[n,:].K[m,:]   (bf16 3-product)
        gemm_mma<1><<<scoreGrid, 256, GEMM_SMEM>>>(
            (const u16*)Qh, (const u16*)Ql, (const u16*)Kh, (const u16*)Kl,
            DHID, DHID, DHID, qkStride, qkStride,
            S, nullptr, nullptr, nullptr, (long long)NPIX, sStride);

        softmax_h<<<BATCH * NPIX, 256>>>(S, (u16*)A16);

        // out[c,n] = sum_m V[c,m] * attn[n,m]   (fp16 2-product)
        gemm_av<<<avGrid, 256, AV_SMEM>>>(
            (const u16*)Vh, (const u16*)Vl, (const u16*)A16,
            NPIX, NPIX, NPIX, featStride, sStride,
            Cout, (long long)NPIX, outStride);
    }

    const int copyBlocks = (int)(((long long)BATCH * CIN * NPIX / 4 + 255) / 256);
    copy_features<<<copyBlocks, 256>>>(left,  outL);
    copy_features<<<copyBlocks, 256>>>(right, outR);
}

// round 5
// speedup vs baseline: 4.3472x; 1.4646x over previous
#include <cuda_runtime.h>
#include <cuda_bf16.h>
#include <cuda_fp16.h>
#include <math.h>
#include <stdint.h>

typedef unsigned short u16;
typedef unsigned int   u32;
typedef unsigned long long u64;

#define BATCH 4
#define CIN   2048
#define NPIX  2304
#define DHID  256

// ---------------- scratch (static device globals; no allocations) ----------
__device__ u16 g_fL16[(size_t)BATCH*CIN*NPIX];   // left features fp16 single [B][C][N] (V)
__device__ u16 g_fR16[(size_t)BATCH*CIN*NPIX];
__device__ u16 g_fTLhi[(size_t)BATCH*NPIX*CIN];  // transposed [B][N][C] bf16 hi/lo (proj operand)
__device__ u16 g_fTLlo[(size_t)BATCH*NPIX*CIN];
__device__ u16 g_fTRhi[(size_t)BATCH*NPIX*CIN];
__device__ u16 g_fTRlo[(size_t)BATCH*NPIX*CIN];
__device__ u16 g_wqhi[(size_t)DHID*CIN];
__device__ u16 g_wqlo[(size_t)DHID*CIN];
__device__ u16 g_wrhi[(size_t)DHID*CIN];
__device__ u16 g_wrlo[(size_t)DHID*CIN];
__device__ u16 g_QLhi[(size_t)BATCH*NPIX*DHID];
__device__ u16 g_QLlo[(size_t)BATCH*NPIX*DHID];
__device__ u16 g_KRhi[(size_t)BATCH*NPIX*DHID];
__device__ u16 g_KRlo[(size_t)BATCH*NPIX*DHID];
__device__ u16 g_QRhi[(size_t)BATCH*NPIX*DHID];
__device__ u16 g_QRlo[(size_t)BATCH*NPIX*DHID];
__device__ u16 g_KLhi[(size_t)BATCH*NPIX*DHID];
__device__ u16 g_KLlo[(size_t)BATCH*NPIX*DHID];
__device__ float g_S[(size_t)BATCH*NPIX*NPIX];   // fp32 scores
__device__ u16 g_A16[(size_t)BATCH*NPIX*NPIX];   // attn fp16 (single)

// ---------------- helpers ----------------------------------------------------
__device__ __forceinline__ u32 smem_u32(const void* p) {
    u32 a;
    asm("{ .reg .u64 t; cvta.to.shared.u64 t, %1; cvt.u32.u64 %0, t; }" : "=r"(a) : "l"(p));
    return a;
}
__device__ __forceinline__ void cp16(u32 dst, const void* src) {
    asm volatile("cp.async.cg.shared.global [%0], [%1], 16;" :: "r"(dst), "l"(src));
}
__device__ __forceinline__ void cp_commit() {
    asm volatile("cp.async.commit_group;" ::: "memory");
}
__device__ __forceinline__ void cp_wait2() {
    asm volatile("cp.async.wait_group 2;" ::: "memory");
}
__device__ __forceinline__ void cp_wait3() {
    asm volatile("cp.async.wait_group 3;" ::: "memory");
}
__device__ __forceinline__ void ldsm_x4(u32& r0, u32& r1, u32& r2, u32& r3, u32 addr) {
    asm volatile("ldmatrix.sync.aligned.m8n8.x4.shared.b16 {%0,%1,%2,%3}, [%4];"
                 : "=r"(r0), "=r"(r1), "=r"(r2), "=r"(r3) : "r"(addr));
}
__device__ __forceinline__ void mma_bf16(float* d, const u32* a, u32 b0, u32 b1) {
    asm volatile(
        "mma.sync.aligned.m16n8k16.row.col.f32.bf16.bf16.f32 "
        "{%0,%1,%2,%3}, {%4,%5,%6,%7}, {%8,%9}, {%0,%1,%2,%3};"
        : "+f"(d[0]), "+f"(d[1]), "+f"(d[2]), "+f"(d[3])
        : "r"(a[0]), "r"(a[1]), "r"(a[2]), "r"(a[3]), "r"(b0), "r"(b1));
}
__device__ __forceinline__ void mma_f16(float* d, const u32* a, u32 b0, u32 b1) {
    asm volatile(
        "mma.sync.aligned.m16n8k16.row.col.f32.f16.f16.f32 "
        "{%0,%1,%2,%3}, {%4,%5,%6,%7}, {%8,%9}, {%0,%1,%2,%3};"
        : "+f"(d[0]), "+f"(d[1]), "+f"(d[2]), "+f"(d[3])
        : "r"(a[0]), "r"(a[1]), "r"(a[2]), "r"(a[3]), "r"(b0), "r"(b1));
}
__device__ __forceinline__ void split2(float v, u16& h, u16& l) {   // bf16 split
    __nv_bfloat16 hb = __float2bfloat16(v);
    float r = v - __bfloat162float(hb);
    __nv_bfloat16 lb = __float2bfloat16(r);
    h = *reinterpret_cast<u16*>(&hb);
    l = *reinterpret_cast<u16*>(&lb);
}
// swizzled byte offset inside a 128x32 16-bit tile (row stride 64B, 4x16B chunks)
__device__ __forceinline__ u32 swz(int row, int ch) {
    return (u32)(row * 64 + ((ch ^ ((row >> 1) & 3)) << 4));
}

// ============================================================================
// GEMM A: bf16 3-product (hi*hi + hi*lo + lo*hi), CTA 128x128x32, 3 stages.
// MODE 0: out = bf16 hi/lo (+bias[n])     MODE 1: out = fp32
// ============================================================================
#define STAGES 3
#define STAGE_BYTES 32768
#define AHI_OFF 0
#define ALO_OFF 8192
#define BHI_OFF 16384
#define BLO_OFF 24576
#define GEMM_SMEM (STAGES * STAGE_BYTES)

template<int MODE>
__global__ __launch_bounds__(256, 1)
void gemm_mma(const u16* __restrict__ Ahi, const u16* __restrict__ Alo,
              const u16* __restrict__ Bhi, const u16* __restrict__ Blo,
              int K, int lda, int ldb,
              long long strideA, long long strideB,
              float* __restrict__ C, const float* __restrict__ bias,
              u16* __restrict__ Chi, u16* __restrict__ Clo,
              long long ldc, long long strideC)
{
    extern __shared__ char smem[];
    const u32 sb = smem_u32(smem);
    const int tid = threadIdx.x, lane = tid & 31, wid = tid >> 5;
    const int m0 = blockIdx.y * 128, n0 = blockIdx.x * 128, bz = blockIdx.z;

    Ahi += (long long)bz * strideA;  Alo += (long long)bz * strideA;
    Bhi += (long long)bz * strideB;  Blo += (long long)bz * strideB;

    const int KT = K >> 5;

    const int r0l = tid >> 2,         c0l = tid & 3;
    const int r1l = (tid + 256) >> 2, c1l = tid & 3;
    const u32 o0 = swz(r0l, c0l), o1 = swz(r1l, c1l);

    auto load_stage = [&](int kt, int s) {
        const u32 base = sb + s * STAGE_BYTES;
        const int kc = kt * 32;
        {
            const long long ao = (long long)(m0 + r0l) * lda + kc + c0l * 8;
            const long long bo = (long long)(n0 + r0l) * ldb + kc + c0l * 8;
            cp16(base + AHI_OFF + o0, Ahi + ao);
            cp16(base + ALO_OFF + o0, Alo + ao);
            cp16(base + BHI_OFF + o0, Bhi + bo);
            cp16(base + BLO_OFF + o0, Blo + bo);
        }
        {
            const long long ao = (long long)(m0 + r1l) * lda + kc + c1l * 8;
            const long long bo = (long long)(n0 + r1l) * ldb + kc + c1l * 8;
            cp16(base + AHI_OFF + o1, Ahi + ao);
            cp16(base + ALO_OFF + o1, Alo + ao);
            cp16(base + BHI_OFF + o1, Bhi + bo);
            cp16(base + BLO_OFF + o1, Blo + bo);
        }
    };

    float acc[2][8][4];
#pragma unroll
    for (int i = 0; i < 2; ++i)
#pragma unroll
        for (int j = 0; j < 8; ++j)
#pragma unroll
            for (int q = 0; q < 4; ++q) acc[i][j][q] = 0.f;

    const int wm = (wid & 3) * 32;
    const int wn = (wid >> 2) * 64;
    const int aRow = (lane & 15);
    const int kHi  = (lane >> 4);
    const int bRow = (lane & 7) + ((lane >> 3) & 1) * 8;

#pragma unroll
    for (int p = 0; p < STAGES; ++p) { load_stage(p, p); cp_commit(); }

    int s = 0;
    for (int kt = 0; kt < KT; ++kt) {
        cp_wait2();
        __syncthreads();
        const u32 base = sb + s * STAGE_BYTES;

#pragma unroll
        for (int k16 = 0; k16 < 2; ++k16) {
            const int kc = k16 * 2 + kHi;
            u32 ah[2][4], al[2][4];
#pragma unroll
            for (int mt = 0; mt < 2; ++mt) {
                const u32 off = swz(wm + mt * 16 + aRow, kc);
                ldsm_x4(ah[mt][0], ah[mt][1], ah[mt][2], ah[mt][3], base + AHI_OFF + off);
                ldsm_x4(al[mt][0], al[mt][1], al[mt][2], al[mt][3], base + ALO_OFF + off);
            }
            u32 bh[8][2], bl[8][2];
#pragma unroll
            for (int nt4 = 0; nt4 < 4; ++nt4) {
                const u32 off = swz(wn + nt4 * 16 + bRow, kc);
                u32 x0, x1, x2, x3;
                ldsm_x4(x0, x1, x2, x3, base + BHI_OFF + off);
                bh[nt4*2][0] = x0; bh[nt4*2][1] = x2;
                bh[nt4*2+1][0] = x1; bh[nt4*2+1][1] = x3;
                ldsm_x4(x0, x1, x2, x3, base + BLO_OFF + off);
                bl[nt4*2][0] = x0; bl[nt4*2][1] = x2;
                bl[nt4*2+1][0] = x1; bl[nt4*2+1][1] = x3;
            }
#pragma unroll
            for (int mt = 0; mt < 2; ++mt)
#pragma unroll
                for (int nt = 0; nt < 8; ++nt) {
                    mma_bf16(acc[mt][nt], ah[mt], bh[nt][0], bh[nt][1]);
                    mma_bf16(acc[mt][nt], ah[mt], bl[nt][0], bl[nt][1]);
                    mma_bf16(acc[mt][nt], al[mt], bh[nt][0], bh[nt][1]);
                }
        }
        __syncthreads();
        if (kt + STAGES < KT) load_stage(kt + STAGES, s);
        cp_commit();
        s = (s == STAGES - 1) ? 0 : s + 1;
    }

    const int tq = lane >> 2;
    const int tr = (lane & 3) * 2;
#pragma unroll
    for (int mt = 0; mt < 2; ++mt) {
#pragma unroll
        for (int nt = 0; nt < 8; ++nt) {
            const int m = m0 + wm + mt * 16 + tq;
            const int n = n0 + wn + nt * 8 + tr;
            const float* a = acc[mt][nt];
            const long long b0 = (long long)bz * strideC + (long long)m * ldc + n;
            const long long b1 = b0 + 8 * ldc;
            if (MODE == 1) {
                *reinterpret_cast<float2*>(C + b0) = make_float2(a[0], a[1]);
                *reinterpret_cast<float2*>(C + b1) = make_float2(a[2], a[3]);
            } else {
                const float bv0 = bias[n], bv1 = bias[n + 1];
                u16 h0, l0, h1, l1;
                split2(a[0] + bv0, h0, l0); split2(a[1] + bv1, h1, l1);
                *reinterpret_cast<u32*>(Chi + b0) = (u32)h0 | ((u32)h1 << 16);
                *reinterpret_cast<u32*>(Clo + b0) = (u32)l0 | ((u32)l1 << 16);
                split2(a[2] + bv0, h0, l0); split2(a[3] + bv1, h1, l1);
                *reinterpret_cast<u32*>(Chi + b1) = (u32)h0 | ((u32)h1 << 16);
                *reinterpret_cast<u32*>(Clo + b1) = (u32)l0 | ((u32)l1 << 16);
            }
        }
    }
}

// ============================================================================
// GEMM B (attn.V): single-product fp16 — A = V fp16, B = attn fp16.
// out[m,n] = sum_k A[m,k]*B[n,k], fp32 out. CTA 128x128x32, 4 stages, 2 CTA/SM.
// ============================================================================
#define AV_STAGES 4
#define AV_STAGE_BYTES 16384
#define AV_A 0
#define AV_B 8192
#define AV_SMEM (AV_STAGES * AV_STAGE_BYTES)

__global__ __launch_bounds__(256, 2)
void gemm_av(const u16* __restrict__ A, const u16* __restrict__ B,
             int K, int lda, int ldb,
             long long strideA, long long strideB,
             float* __restrict__ C, long long ldc, long long strideC)
{
    extern __shared__ char smem[];
    const u32 sb = smem_u32(smem);
    const int tid = threadIdx.x, lane = tid & 31, wid = tid >> 5;
    const int m0 = blockIdx.y * 128, n0 = blockIdx.x * 128, bz = blockIdx.z;

    A += (long long)bz * strideA;
    B += (long long)bz * strideB;

    const int KT = K >> 5;  // 72

    const int r0l = tid >> 2,         c0l = tid & 3;
    const int r1l = (tid + 256) >> 2, c1l = tid & 3;
    const u32 o0 = swz(r0l, c0l), o1 = swz(r1l, c1l);

    auto load_stage = [&](int kt, int s) {
        const u32 base = sb + s * AV_STAGE_BYTES;
        const int kc = kt * 32;
        {
            const long long ao = (long long)(m0 + r0l) * lda + kc + c0l * 8;
            const long long bo = (long long)(n0 + r0l) * ldb + kc + c0l * 8;
            cp16(base + AV_A + o0, A + ao);
            cp16(base + AV_B + o0, B + bo);
        }
        {
            const long long ao = (long long)(m0 + r1l) * lda + kc + c1l * 8;
            const long long bo = (long long)(n0 + r1l) * ldb + kc + c1l * 8;
            cp16(base + AV_A + o1, A + ao);
            cp16(base + AV_B + o1, B + bo);
        }
    };

    float acc[2][8][4];
#pragma unroll
    for (int i = 0; i < 2; ++i)
#pragma unroll
        for (int j = 0; j < 8; ++j)
#pragma unroll
            for (int q = 0; q < 4; ++q) acc[i][j][q] = 0.f;

    const int wm = (wid & 3) * 32;
    const int wn = (wid >> 2) * 64;
    const int aRow = (lane & 15);
    const int kHi  = (lane >> 4);
    const int bRow = (lane & 7) + ((lane >> 3) & 1) * 8;

#pragma unroll
    for (int p = 0; p < AV_STAGES; ++p) { load_stage(p, p); cp_commit(); }

    int s = 0;
    for (int kt = 0; kt < KT; ++kt) {
        cp_wait3();
        __syncthreads();
        const u32 base = sb + s * AV_STAGE_BYTES;

#pragma unroll
        for (int k16 = 0; k16 < 2; ++k16) {
            const int kc = k16 * 2 + kHi;
            u32 ah[2][4];
#pragma unroll
            for (int mt = 0; mt < 2; ++mt) {
                const u32 off = swz(wm + mt * 16 + aRow, kc);
                ldsm_x4(ah[mt][0], ah[mt][1], ah[mt][2], ah[mt][3], base + AV_A + off);
            }
            u32 bb[8][2];
#pragma unroll
            for (int nt4 = 0; nt4 < 4; ++nt4) {
                const u32 off = swz(wn + nt4 * 16 + bRow, kc);
                u32 x0, x1, x2, x3;
                ldsm_x4(x0, x1, x2, x3, base + AV_B + off);
                bb[nt4*2][0] = x0; bb[nt4*2][1] = x2;
                bb[nt4*2+1][0] = x1; bb[nt4*2+1][1] = x3;
            }
#pragma unroll
            for (int mt = 0; mt < 2; ++mt)
#pragma unroll
                for (int nt = 0; nt < 8; ++nt)
                    mma_f16(acc[mt][nt], ah[mt], bb[nt][0], bb[nt][1]);
        }
        __syncthreads();
        if (kt + AV_STAGES < KT) load_stage(kt + AV_STAGES, s);
        cp_commit();
        s = (s == AV_STAGES - 1) ? 0 : s + 1;
    }

    const int tq = lane >> 2;
    const int tr = (lane & 3) * 2;
#pragma unroll
    for (int mt = 0; mt < 2; ++mt) {
#pragma unroll
        for (int nt = 0; nt < 8; ++nt) {
            const int m = m0 + wm + mt * 16 + tq;
            const int n = n0 + wn + nt * 8 + tr;
            const float* a = acc[mt][nt];
            const long long b0 = (long long)bz * strideC + (long long)m * ldc + n;
            const long long b1 = b0 + 8 * ldc;
            *reinterpret_cast<float2*>(C + b0) = make_float2(a[0], a[1]);
            *reinterpret_cast<float2*>(C + b1) = make_float2(a[2], a[3]);
        }
    }
}

// ---------------- conversion kernels -----------------------------------------
// fp32 -> fp16 single (for V operands)
__global__ __launch_bounds__(256)
void cvt4h(const float4* __restrict__ src, uint2* __restrict__ dst, long long n4)
{
    long long i = (long long)blockIdx.x * 256 + threadIdx.x;
    if (i >= n4) return;
    float4 v = src[i];
    __half2 p0 = __floats2half2_rn(v.x, v.y);
    __half2 p1 = __floats2half2_rn(v.z, v.w);
    dst[i] = make_uint2(*reinterpret_cast<u32*>(&p0), *reinterpret_cast<u32*>(&p1));
}
// fp32 -> bf16 hi/lo (for weights)
__global__ __launch_bounds__(256)
void split4(const float4* __restrict__ src, uint2* __restrict__ hi, uint2* __restrict__ lo, long long n4)
{
    long long i = (long long)blockIdx.x * 256 + threadIdx.x;
    if (i >= n4) return;
    float4 v = src[i];
    u16 h0,l0,h1,l1,h2,l2,h3,l3;
    split2(v.x,h0,l0); split2(v.y,h1,l1); split2(v.z,h2,l2); split2(v.w,h3,l3);
    hi[i] = make_uint2((u32)h0 | ((u32)h1 << 16), (u32)h2 | ((u32)h3 << 16));
    lo[i] = make_uint2((u32)l0 | ((u32)l1 << 16), (u32)l2 | ((u32)l3 << 16));
}

// X [B][C][N] fp32 -> XT [B][N][C] bf16 hi/lo
__global__ __launch_bounds__(256)
void transpose_split(const float* __restrict__ X, u16* __restrict__ hi, u16* __restrict__ lo)
{
    __shared__ float tile[32][33];
    const int b  = blockIdx.z;
    const int n0 = blockIdx.x * 32;
    const int c0 = blockIdx.y * 32;
    const int tx = threadIdx.x, ty = threadIdx.y;
    const float* src = X + ((long long)b * CIN + c0) * NPIX + n0;
#pragma unroll
    for (int r = 0; r < 32; r += 8)
        tile[ty + r][tx] = src[(long long)(ty + r) * NPIX + tx];
    __syncthreads();
#pragma unroll
    for (int r = 0; r < 32; r += 8) {
        float v = tile[tx][ty + r];
        u16 h, l; split2(v, h, l);
        long long o = ((long long)b * NPIX + n0 + ty + r) * CIN + c0 + tx;
        hi[o] = h; lo[o] = l;
    }
}

// row softmax fp32 -> attn fp16 single
__global__ __launch_bounds__(256)
void softmax_h(const float* __restrict__ S, u16* __restrict__ A)
{
    const int PER = NPIX / 256;  // 9
    const long long rb = (long long)blockIdx.x * NPIX;
    const float* p = S + rb;
    const int tid = threadIdx.x;

    float v[PER];
    float mx = -INFINITY;
#pragma unroll
    for (int i = 0; i < PER; ++i) { v[i] = p[tid + i*256]; mx = fmaxf(mx, v[i]); }

    __shared__ float red[8];
#pragma unroll
    for (int o = 16; o; o >>= 1) mx = fmaxf(mx, __shfl_xor_sync(0xffffffffu, mx, o));
    if ((tid & 31) == 0) red[tid >> 5] = mx;
    __syncthreads();
    mx = red[0];
#pragma unroll
    for (int i = 1; i < 8; ++i) mx = fmaxf(mx, red[i]);
    __syncthreads();

    float s = 0.f;
#pragma unroll
    for (int i = 0; i < PER; ++i) { v[i] = __expf(v[i] - mx); s += v[i]; }
#pragma unroll
    for (int o = 16; o; o >>= 1) s += __shfl_xor_sync(0xffffffffu, s, o);
    if ((tid & 31) == 0) red[tid >> 5] = s;
    __syncthreads();
    s = red[0];
#pragma unroll
    for (int i = 1; i < 8; ++i) s += red[i];

    const float inv = 1.f / s;
#pragma unroll
    for (int i = 0; i < PER; ++i) {
        __half h = __float2half_rn(v[i] * inv);
        A[rb + tid + i*256] = *reinterpret_cast<u16*>(&h);
    }
}

__global__ __launch_bounds__(256)
void copy_features(const float* __restrict__ src, float* __restrict__ dst)
{
    const long long perBatch4 = (long long)CIN * NPIX / 4;
    const long long total4 = (long long)BATCH * perBatch4;
    long long idx = (long long)blockIdx.x * blockDim.x + threadIdx.x;
    if (idx >= total4) return;
    long long b = idx / perBatch4;
    long long r = idx % perBatch4;
    reinterpret_cast<float4*>(dst)[b * ((long long)2 * CIN * NPIX / 4) + r] =
        reinterpret_cast<const float4*>(src)[idx];
}

// ---------------- host --------------------------------------------------------
extern "C" void kernel_launch(void* const* d_in, const int* in_sizes, int n_in,
                              void* d_out, int out_size)
{
    const float* left  = (const float*)d_in[0];
    const float* right = (const float*)d_in[1];
    const float* wq    = (const float*)d_in[2];
    const float* bq    = (const float*)d_in[3];
    const float* wr    = (const float*)d_in[4];
    const float* br    = (const float*)d_in[5];
    float* out = (float*)d_out;

    void *fL16, *fR16, *fTLhi, *fTLlo, *fTRhi, *fTRlo;
    void *wqhi, *wqlo, *wrhi, *wrlo;
    void *QLhi, *QLlo, *KRhi, *KRlo, *QRhi, *QRlo, *KLhi, *KLlo;
    void *Sraw, *A16;
    cudaGetSymbolAddress(&fL16, g_fL16);   cudaGetSymbolAddress(&fR16, g_fR16);
    cudaGetSymbolAddress(&fTLhi, g_fTLhi); cudaGetSymbolAddress(&fTLlo, g_fTLlo);
    cudaGetSymbolAddress(&fTRhi, g_fTRhi); cudaGetSymbolAddress(&fTRlo, g_fTRlo);
    cudaGetSymbolAddress(&wqhi, g_wqhi);   cudaGetSymbolAddress(&wqlo, g_wqlo);
    cudaGetSymbolAddress(&wrhi, g_wrhi);   cudaGetSymbolAddress(&wrlo, g_wrlo);
    cudaGetSymbolAddress(&QLhi, g_QLhi);   cudaGetSymbolAddress(&QLlo, g_QLlo);
    cudaGetSymbolAddress(&KRhi, g_KRhi);   cudaGetSymbolAddress(&KRlo, g_KRlo);
    cudaGetSymbolAddress(&QRhi, g_QRhi);   cudaGetSymbolAddress(&QRlo, g_QRlo);
    cudaGetSymbolAddress(&KLhi, g_KLhi);   cudaGetSymbolAddress(&KLlo, g_KLlo);
    cudaGetSymbolAddress(&Sraw, g_S);
    cudaGetSymbolAddress(&A16, g_A16);
    float* S = (float*)Sraw;

    cudaFuncSetAttribute(gemm_mma<0>, cudaFuncAttributeMaxDynamicSharedMemorySize, GEMM_SMEM);
    cudaFuncSetAttribute(gemm_mma<1>, cudaFuncAttributeMaxDynamicSharedMemorySize, GEMM_SMEM);
    cudaFuncSetAttribute(gemm_av, cudaFuncAttributeMaxDynamicSharedMemorySize, AV_SMEM);

    // ---- conversions ----
    {
        long long nW4 = (long long)DHID * CIN / 4;
        split4<<<(unsigned)((nW4 + 255) / 256), 256>>>((const float4*)wq, (uint2*)wqhi, (uint2*)wqlo, nW4);
        split4<<<(unsigned)((nW4 + 255) / 256), 256>>>((const float4*)wr, (uint2*)wrhi, (uint2*)wrlo, nW4);
        long long nF4 = (long long)BATCH * CIN * NPIX / 4;
        cvt4h<<<(unsigned)((nF4 + 255) / 256), 256>>>((const float4*)left,  (uint2*)fL16, nF4);
        cvt4h<<<(unsigned)((nF4 + 255) / 256), 256>>>((const float4*)right, (uint2*)fR16, nF4);
        dim3 tg(NPIX / 32, CIN / 32, BATCH);
        transpose_split<<<tg, dim3(32, 8)>>>(left,  (u16*)fTLhi, (u16*)fTLlo);
        transpose_split<<<tg, dim3(32, 8)>>>(right, (u16*)fTRhi, (u16*)fTRlo);
    }

    const long long featStride = (long long)CIN * NPIX;
    const long long qkStride   = (long long)NPIX * DHID;
    const long long sStride    = (long long)NPIX * NPIX;
    const long long outStride  = 2LL * CIN * NPIX;
    float* outL = out;
    float* outR = out + (long long)BATCH * outStride;

    // ---- projections (bf16 3-product): Q[b,n,d] = featT[b,n,:] . W[d,:] + bias ----
    {
        dim3 grid(DHID / 128, NPIX / 128, BATCH);
        struct { void *ah, *al, *bh, *bl; const float* bias; void *ch, *cl; } cfg[4] = {
            {fTLhi, fTLlo, wqhi, wqlo, bq, QLhi, QLlo},
            {fTRhi, fTRlo, wrhi, wrlo, br, KRhi, KRlo},
            {fTRhi, fTRlo, wqhi, wqlo, bq, QRhi, QRlo},
            {fTLhi, fTLlo, wrhi, wrlo, br, KLhi, KLlo},
        };
        for (int i = 0; i < 4; ++i) {
            gemm_mma<0><<<grid, 256, GEMM_SMEM>>>(
                (const u16*)cfg[i].ah, (const u16*)cfg[i].al,
                (const u16*)cfg[i].bh, (const u16*)cfg[i].bl,
                CIN, CIN, CIN, (long long)NPIX * CIN, 0LL,
                nullptr, cfg[i].bias, (u16*)cfg[i].ch, (u16*)cfg[i].cl,
                (long long)DHID, qkStride);
        }
    }

    dim3 scoreGrid(NPIX / 128, NPIX / 128, BATCH);
    dim3 avGrid(NPIX / 128, CIN / 128, BATCH);

    for (int dir = 0; dir < 2; ++dir) {
        void* Qh = dir == 0 ? QLhi : QRhi;  void* Ql = dir == 0 ? QLlo : QRlo;
        void* Kh = dir == 0 ? KRhi : KLhi;  void* Kl = dir == 0 ? KRlo : KLlo;
        void* V16 = dir == 0 ? fR16 : fL16;
        float* Cout = (dir == 0 ? outL : outR) + (long long)CIN * NPIX;

        // scores[n,m] = Q[n,:].K[m,:]   (bf16 3-product)
        gemm_mma<1><<<scoreGrid, 256, GEMM_SMEM>>>(
            (const u16*)Qh, (const u16*)Ql, (const u16*)Kh, (const u16*)Kl,
            DHID, DHID, DHID, qkStride, qkStride,
            S, nullptr, nullptr, nullptr, (long long)NPIX, sStride);

        softmax_h<<<BATCH * NPIX, 256>>>(S, (u16*)A16);

        // out[c,n] = sum_m V[c,m] * attn[n,m]   (fp16 single product)
        gemm_av<<<avGrid, 256, AV_SMEM>>>(
            (const u16*)V16, (const u16*)A16,
            NPIX, NPIX, NPIX, featStride, sStride,
            Cout, (long long)NPIX, outStride);
    }

    const int copyBlocks = (int)(((long long)BATCH * CIN * NPIX / 4 + 255) / 256);
    copy_features<<<copyBlocks, 256>>>(left,  outL);
    copy_features<<<copyBlocks, 256>>>(right, outR);
}